// round 7
// baseline (speedup 1.0000x reference)
#include <cuda_runtime.h>

typedef unsigned long long ULL;

// ---------------- f32x2 helpers (Blackwell packed fp32) ----------------
__device__ __forceinline__ ULL pk2(float a, float b) {
    ULL r; asm("mov.b64 %0, {%1, %2};" : "=l"(r) : "f"(a), "f"(b)); return r;
}
__device__ __forceinline__ void upk2(ULL v, float& a, float& b) {
    asm("mov.b64 {%0, %1}, %2;" : "=f"(a), "=f"(b) : "l"(v));
}
#define FMA2(acc, a, b) asm("fma.rn.f32x2 %0, %1, %2, %0;" : "+l"(acc) : "l"(a), "l"(b))
#define ADD2(acc, b)    asm("add.rn.f32x2 %0, %0, %1;"     : "+l"(acc) : "l"(b))

// ---------------- problem constants ----------------
constexpr int B_   = 4096;
constexpr int T_   = 128;
constexpr int I_   = 28;
constexpr int O_   = 10;
constexpr int RPB  = 32;           // batch rows per block
constexpr int NBLK = B_ / RPB;     // 128 blocks, 1 per SM
constexpr int NTHR = 512;          // 2 k-sets x 4 row-groups x 64 units
constexpr int LDH  = 36;           // h row stride (floats), mult of 4 (aligned float4 stores)
constexpr int XLD  = 36;           // x row stride

// k split: set 0 -> hh k 0..45 ; set 1 -> hh k 46..63 + ih k 0..27  (46 each)
constexpr int KSPL = 46;

// shared memory layout (floats)
constexpr int WS_ELE = 92 * 256;                 // Ws[k][j*4+q]; k 0..63 hh, 64..91 ih
constexpr int HT_OFF = WS_ELE;                   // hT[2][64][LDH]
constexpr int XT_OFF = HT_OFF + 2 * 64 * LDH;    // xT[2][28][XLD]
constexpr int XC_OFF = XT_OFF + 2 * 28 * XLD;    // exchange: 16 slots x 258 ULLs (as 2 floats each)
constexpr int SM_FLOATS = XC_OFF + 16 * 258 * 2; // total ~150 KB

// ---------------- activations (accurate, exp-based; identical math since R1) ----------------
__device__ __forceinline__ float sigf(float x) {
    return __fdividef(1.0f, 1.0f + __expf(-x));
}
__device__ __forceinline__ float tanh_(float x) {
    float ax = fabsf(x);
    float e  = __expf(-2.0f * ax);
    float r  = __fdividef(1.0f - e, 1.0f + e);
    return copysignf(r, x);
}

__global__ void __launch_bounds__(NTHR, 1) lstm_fused(
    const float* __restrict__ x,     // [B, T, I]
    const float* __restrict__ Wih,   // [4H, I]
    const float* __restrict__ Whh,   // [4H, H]
    const float* __restrict__ bih,   // [4H]
    const float* __restrict__ bhh,   // [4H]
    const float* __restrict__ Wout,  // [O, H]
    const float* __restrict__ bout,  // [O]
    float* __restrict__ out)         // [B, O]
{
    extern __shared__ float sm[];
    float* Ws = sm;
    float* hT = sm + HT_OFF;
    float* xT = sm + XT_OFF;
    ULL*   xc = reinterpret_cast<ULL*>(sm + XC_OFF);

    const int tid   = threadIdx.x;
    const int j     = tid & 63;        // hidden unit
    const int g     = tid >> 6;        // 0..7
    const int kset  = g >> 2;          // 0 or 1 (warps 0-7 / 8-15)
    const int ty    = g & 3;           // row group
    const int rbase = ty * 8;          // 8 rows per thread in GEMV
    const int soff  = kset * 4;        // kept-row offset within the 8
    const int lane  = ty * 64 + j;     // 0..255, unique within a set
    const int row0  = blockIdx.x * RPB;

    // ---- stage weights into SMEM, gate-interleaved: Ws[k][j*4 + q] ----
    for (int idx = tid; idx < 256 * 64; idx += NTHR) {        // Whh: idx = g*64 + k
        int gg = idx >> 6, k = idx & 63;
        Ws[k * 256 + (gg & 63) * 4 + (gg >> 6)] = Whh[idx];
    }
    for (int idx = tid; idx < 256 * 28; idx += NTHR) {        // Wih: idx = g*28 + k
        int gg = idx / 28, k = idx - gg * 28;
        Ws[(64 + k) * 256 + (gg & 63) * 4 + (gg >> 6)] = Wih[idx];
    }
    for (int idx = tid; idx < 2 * 64 * LDH; idx += NTHR) hT[idx] = 0.0f;

    // biases (combined) for this unit
    const float b0 = bih[j]       + bhh[j];
    const float b1 = bih[64 + j]  + bhh[64 + j];
    const float b2 = bih[128 + j] + bhh[128 + j];
    const float b3 = bih[192 + j] + bhh[192 + j];

    // ---- preload x for t = 0 into buffer 0 ----  (RPB*I = 896 elements)
    #pragma unroll
    for (int u = 0; u < 2; ++u) {
        int e = u * NTHR + tid;
        if (e < RPB * I_) {
            int r = e / 28, i2 = e - r * 28;
            xT[i2 * XLD + r] = x[(row0 + r) * (T_ * I_) + 0 * I_ + i2];
        }
    }
    __syncthreads();

    float creg[4];   // cell state for the 4 rows this thread owns in the epilogue
    #pragma unroll
    for (int r = 0; r < 4; ++r) creg[r] = 0.0f;

    // =================== time loop ===================
    for (int t = 0; t < T_; ++t) {
        // prefetch x for t+1
        float xn[2];
        const bool pf = (t + 1 < T_);
        if (pf) {
            #pragma unroll
            for (int u = 0; u < 2; ++u) {
                int e  = u * NTHR + tid;
                int e2 = (e < RPB * I_) ? e : 0;
                int r = e2 / 28, i2 = e2 - r * 28;
                xn[u] = x[(row0 + r) * (T_ * I_) + (t + 1) * I_ + i2];
            }
        }

        const float* xb = xT + (t & 1) * 28 * XLD;
        const float* hb = hT + (t & 1) * 64 * LDH;

        // accumulators: [row-pair rp][gate q]; lanes = (row 2rp, row 2rp+1) of this thread's 8
        ULL acc[4][4];
        #pragma unroll
        for (int rp = 0; rp < 4; ++rp)
            #pragma unroll
            for (int q = 0; q < 4; ++q)
                acc[rp][q] = 0ULL;

        if (kset == 0) {
            // ---- k = 0..45 of the recurrent part ----
            #pragma unroll 8
            for (int k = 0; k < KSPL; ++k) {
                const float4 w4 = *reinterpret_cast<const float4*>(Ws + k * 256 + j * 4);
                const ULL* hp = reinterpret_cast<const ULL*>(hb + k * LDH + rbase);
                const ULL h0 = hp[0], h1 = hp[1], h2 = hp[2], h3 = hp[3];
                const ULL w0 = pk2(w4.x, w4.x), w1 = pk2(w4.y, w4.y);
                const ULL w2 = pk2(w4.z, w4.z), w3 = pk2(w4.w, w4.w);
                FMA2(acc[0][0], h0, w0); FMA2(acc[0][1], h0, w1); FMA2(acc[0][2], h0, w2); FMA2(acc[0][3], h0, w3);
                FMA2(acc[1][0], h1, w0); FMA2(acc[1][1], h1, w1); FMA2(acc[1][2], h1, w2); FMA2(acc[1][3], h1, w3);
                FMA2(acc[2][0], h2, w0); FMA2(acc[2][1], h2, w1); FMA2(acc[2][2], h2, w2); FMA2(acc[2][3], h2, w3);
                FMA2(acc[3][0], h3, w0); FMA2(acc[3][1], h3, w1); FMA2(acc[3][2], h3, w2); FMA2(acc[3][3], h3, w3);
            }
        } else {
            // ---- k = 46..63 of the recurrent part ----
            #pragma unroll 6
            for (int k = KSPL; k < 64; ++k) {
                const float4 w4 = *reinterpret_cast<const float4*>(Ws + k * 256 + j * 4);
                const ULL* hp = reinterpret_cast<const ULL*>(hb + k * LDH + rbase);
                const ULL h0 = hp[0], h1 = hp[1], h2 = hp[2], h3 = hp[3];
                const ULL w0 = pk2(w4.x, w4.x), w1 = pk2(w4.y, w4.y);
                const ULL w2 = pk2(w4.z, w4.z), w3 = pk2(w4.w, w4.w);
                FMA2(acc[0][0], h0, w0); FMA2(acc[0][1], h0, w1); FMA2(acc[0][2], h0, w2); FMA2(acc[0][3], h0, w3);
                FMA2(acc[1][0], h1, w0); FMA2(acc[1][1], h1, w1); FMA2(acc[1][2], h1, w2); FMA2(acc[1][3], h1, w3);
                FMA2(acc[2][0], h2, w0); FMA2(acc[2][1], h2, w1); FMA2(acc[2][2], h2, w2); FMA2(acc[2][3], h2, w3);
                FMA2(acc[3][0], h3, w0); FMA2(acc[3][1], h3, w1); FMA2(acc[3][2], h3, w2); FMA2(acc[3][3], h3, w3);
            }
            // ---- input part: all 28 input k's ----
            #pragma unroll 7
            for (int k = 0; k < I_; ++k) {
                const float4 w4 = *reinterpret_cast<const float4*>(Ws + (64 + k) * 256 + j * 4);
                const ULL* xp = reinterpret_cast<const ULL*>(xb + k * XLD + rbase);
                const ULL h0 = xp[0], h1 = xp[1], h2 = xp[2], h3 = xp[3];
                const ULL w0 = pk2(w4.x, w4.x), w1 = pk2(w4.y, w4.y);
                const ULL w2 = pk2(w4.z, w4.z), w3 = pk2(w4.w, w4.w);
                FMA2(acc[0][0], h0, w0); FMA2(acc[0][1], h0, w1); FMA2(acc[0][2], h0, w2); FMA2(acc[0][3], h0, w3);
                FMA2(acc[1][0], h1, w0); FMA2(acc[1][1], h1, w1); FMA2(acc[1][2], h1, w2); FMA2(acc[1][3], h1, w3);
                FMA2(acc[2][0], h2, w0); FMA2(acc[2][1], h2, w1); FMA2(acc[2][2], h2, w2); FMA2(acc[2][3], h2, w3);
                FMA2(acc[3][0], h3, w0); FMA2(acc[3][1], h3, w1); FMA2(acc[3][2], h3, w2); FMA2(acc[3][3], h3, w3);
            }
        }

        // ---- exchange: ship the 4 rows (2 row-pairs) this thread does NOT keep ----
        // set 0 keeps rp 0,1 (rows rbase+0..3), sends rp 2,3; set 1 keeps rp 2,3, sends rp 0,1.
        const int send_rp = kset ? 0 : 2;
        const int keep_rp = kset ? 2 : 0;
        #pragma unroll
        for (int q = 0; q < 4; ++q)
            #pragma unroll
            for (int p = 0; p < 2; ++p)
                xc[((q * 2 + p) * 2 + kset) * 258 + lane] = acc[send_rp + p][q];
        __syncthreads();
        #pragma unroll
        for (int q = 0; q < 4; ++q)
            #pragma unroll
            for (int p = 0; p < 2; ++p) {
                ULL part = xc[((q * 2 + p) * 2 + (1 - kset)) * 258 + lane];
                ADD2(acc[keep_rp + p][q], part);
            }

        // ---- elementwise LSTM cell update on the 4 kept rows ----
        float hnew[4];
        #pragma unroll
        for (int p = 0; p < 2; ++p) {
            float gi0, gi1, gf0, gf1, gg0, gg1, go0, go1;
            upk2(acc[keep_rp + p][0], gi0, gi1);
            upk2(acc[keep_rp + p][1], gf0, gf1);
            upk2(acc[keep_rp + p][2], gg0, gg1);
            upk2(acc[keep_rp + p][3], go0, go1);
            {
                const int r = 2 * p;
                float iv = sigf(gi0 + b0), fv = sigf(gf0 + b1), gv = tanh_(gg0 + b2), ov = sigf(go0 + b3);
                creg[r] = fv * creg[r] + iv * gv;
                hnew[r] = ov * tanh_(creg[r]);
            }
            {
                const int r = 2 * p + 1;
                float iv = sigf(gi1 + b0), fv = sigf(gf1 + b1), gv = tanh_(gg1 + b2), ov = sigf(go1 + b3);
                creg[r] = fv * creg[r] + iv * gv;
                hnew[r] = ov * tanh_(creg[r]);
            }
        }

        // write new h (rows rbase+soff..+3 of unit j) into the other buffer; stage next x
        {
            float4 hv = make_float4(hnew[0], hnew[1], hnew[2], hnew[3]);
            *reinterpret_cast<float4*>(hT + ((t + 1) & 1) * 64 * LDH + j * LDH + rbase + soff) = hv;
        }
        if (pf) {
            float* xb2 = xT + ((t + 1) & 1) * 28 * XLD;
            #pragma unroll
            for (int u = 0; u < 2; ++u) {
                int e = u * NTHR + tid;
                if (e < RPB * I_) {
                    int r = e / 28, i2 = e - r * 28;
                    xb2[i2 * XLD + r] = xn[u];
                }
            }
        }
        __syncthreads();
    }

    // ---- final projection: out[b][o] = h_T[b] . Wout[o] + bout[o] ----
    const float* hf = hT + (T_ & 1) * 64 * LDH;
    for (int idx = tid; idx < RPB * O_; idx += NTHR) {
        int r = idx / O_, o = idx - r * O_;
        float s = bout[o];
        #pragma unroll
        for (int k = 0; k < 64; ++k)
            s += hf[k * LDH + r] * Wout[o * 64 + k];
        out[(row0 + r) * O_ + o] = s;
    }
}

extern "C" void kernel_launch(void* const* d_in, const int* in_sizes, int n_in,
                              void* d_out, int out_size)
{
    const float* x    = (const float*)d_in[0];
    const float* Wih  = (const float*)d_in[1];
    const float* Whh  = (const float*)d_in[2];
    const float* bih  = (const float*)d_in[3];
    const float* bhh  = (const float*)d_in[4];
    const float* Wout = (const float*)d_in[5];
    const float* bout = (const float*)d_in[6];
    float* out = (float*)d_out;

    const size_t smem = (size_t)SM_FLOATS * sizeof(float);  // ~150 KB
    cudaFuncSetAttribute(lstm_fused, cudaFuncAttributeMaxDynamicSharedMemorySize, (int)smem);
    lstm_fused<<<NBLK, NTHR, smem>>>(x, Wih, Whh, bih, bhh, Wout, bout, out);
}

// round 8
// speedup vs baseline: 1.2775x; 1.2775x over previous
#include <cuda_runtime.h>

typedef unsigned long long ULL;

// ---------------- f32x2 helpers (Blackwell packed fp32) ----------------
__device__ __forceinline__ ULL pk2(float a, float b) {
    ULL r; asm("mov.b64 %0, {%1, %2};" : "=l"(r) : "f"(a), "f"(b)); return r;
}
__device__ __forceinline__ void upk2(ULL v, float& a, float& b) {
    asm("mov.b64 {%0, %1}, %2;" : "=f"(a), "=f"(b) : "l"(v));
}
#define FMA2(acc, a, b) asm("fma.rn.f32x2 %0, %1, %2, %0;" : "+l"(acc) : "l"(a), "l"(b))

// ---------------- problem constants ----------------
constexpr int B_  = 4096;
constexpr int T_  = 128;
constexpr int I_  = 28;
constexpr int O_  = 10;
constexpr int RPB = 16;            // batch rows per block
constexpr int NBLK = B_ / RPB;     // 256 blocks (2 CTAs co-resident on most SMs)
constexpr int NTHR = 128;          // 64 units x 2 row-groups
constexpr int LDH  = 18;           // padded row stride (floats), 8B-aligned pairs

// shared memory layout (floats), per CTA
constexpr int WS_ELE  = 92 * 256;             // Ws[k][j*4+q], k: 0..63 = W_hh, 64..91 = W_ih
constexpr int HT_OFF  = WS_ELE;               // hT[2][64][LDH]  double buffer (unit-major)
constexpr int XT_OFF  = HT_OFF + 2 * 64 * LDH; // xT[2][28][LDH] double buffer
constexpr int SM_FLOATS = XT_OFF + 2 * 28 * LDH;   // ~107.5 KB -> two CTAs fit per SM

// ---------------- activations: HW tanh (MUFU.TANH), sigmoid via tanh ----------------
__device__ __forceinline__ float tanhfast(float x) {
    float r; asm("tanh.approx.f32 %0, %1;" : "=f"(r) : "f"(x)); return r;
}
__device__ __forceinline__ float sigf(float x) {
    return fmaf(0.5f, tanhfast(0.5f * x), 0.5f);
}

__global__ void __launch_bounds__(NTHR, 2) lstm_fused(
    const float* __restrict__ x,     // [B, T, I]
    const float* __restrict__ Wih,   // [4H, I]
    const float* __restrict__ Whh,   // [4H, H]
    const float* __restrict__ bih,   // [4H]
    const float* __restrict__ bhh,   // [4H]
    const float* __restrict__ Wout,  // [O, H]
    const float* __restrict__ bout,  // [O]
    float* __restrict__ out)         // [B, O]
{
    extern __shared__ float sm[];
    float* Ws = sm;
    float* hT = sm + HT_OFF;   // two buffers of 64*LDH
    float* xT = sm + XT_OFF;

    const int tid   = threadIdx.x;
    const int j     = tid & 63;   // hidden unit owned by this thread
    const int ty    = tid >> 6;   // row group (0..1), 8 rows each
    const int rbase = ty * 8;
    const int row0  = blockIdx.x * RPB;

    // ---- stage weights into SMEM, gate-interleaved: Ws[k][j*4 + q], q in {i,f,g,o} ----
    for (int idx = tid; idx < 256 * 64; idx += NTHR) {        // W_hh[g][k]
        int g = idx >> 6, k = idx & 63;
        Ws[k * 256 + (g & 63) * 4 + (g >> 6)] = Whh[idx];
    }
    for (int idx = tid; idx < 256 * 28; idx += NTHR) {        // W_ih[g][k]
        int g = idx / 28, k = idx - g * 28;
        Ws[(64 + k) * 256 + (g & 63) * 4 + (g >> 6)] = Wih[idx];
    }
    for (int idx = tid; idx < 2 * 64 * LDH; idx += NTHR) hT[idx] = 0.0f;

    // biases (combined), replicated into f32x2
    const float b0 = bih[j]       + bhh[j];
    const float b1 = bih[64 + j]  + bhh[64 + j];
    const float b2 = bih[128 + j] + bhh[128 + j];
    const float b3 = bih[192 + j] + bhh[192 + j];
    const ULL bb[4] = { pk2(b0, b0), pk2(b1, b1), pk2(b2, b2), pk2(b3, b3) };

    // ---- preload x for t = 0 into buffer 0 ----  (RPB*I = 448 elements, 128 threads)
    #pragma unroll
    for (int u = 0; u < 4; ++u) {
        int e = u * NTHR + tid;
        if (e < RPB * I_) {
            int r = e / 28, i2 = e - r * 28;
            xT[i2 * LDH + r] = x[(row0 + r) * (T_ * I_) + 0 * I_ + i2];
        }
    }
    __syncthreads();

    float creg[8];
    #pragma unroll
    for (int r = 0; r < 8; ++r) creg[r] = 0.0f;

    // =================== time loop (ONE barrier per step) ===================
    for (int t = 0; t < T_; ++t) {
        // prefetch x for t+1 (LDG latency overlaps this step's compute)
        float xn[4];
        const bool pf = (t + 1 < T_);
        if (pf) {
            #pragma unroll
            for (int u = 0; u < 4; ++u) {
                int e = u * NTHR + tid;
                int e2 = (e < RPB * I_) ? e : 0;      // branch-free: clamp, lane 0 dup
                int r = e2 / 28, i2 = e2 - r * 28;
                xn[u] = x[(row0 + r) * (T_ * I_) + (t + 1) * I_ + i2];
            }
        }

        const float* xb = xT + (t & 1) * 28 * LDH;
        const float* hb = hT + (t & 1) * 64 * LDH;   // read buffer

        // accumulators: [row-pair r2][gate-type q], rows packed in f32x2 lanes
        ULL acc[4][4];
        #pragma unroll
        for (int r2 = 0; r2 < 4; ++r2)
            #pragma unroll
            for (int q = 0; q < 4; ++q)
                acc[r2][q] = bb[q];

        // ---- recurrent part: k over hidden units (h_{t-1}) ----
        #pragma unroll 8
        for (int k = 0; k < 64; ++k) {
            const float4 w4 = *reinterpret_cast<const float4*>(Ws + k * 256 + j * 4);
            const ULL* hp = reinterpret_cast<const ULL*>(hb + k * LDH + rbase);
            const ULL h0 = hp[0], h1 = hp[1], h2 = hp[2], h3 = hp[3];
            const ULL w0 = pk2(w4.x, w4.x), w1 = pk2(w4.y, w4.y);
            const ULL w2 = pk2(w4.z, w4.z), w3 = pk2(w4.w, w4.w);
            FMA2(acc[0][0], h0, w0); FMA2(acc[0][1], h0, w1); FMA2(acc[0][2], h0, w2); FMA2(acc[0][3], h0, w3);
            FMA2(acc[1][0], h1, w0); FMA2(acc[1][1], h1, w1); FMA2(acc[1][2], h1, w2); FMA2(acc[1][3], h1, w3);
            FMA2(acc[2][0], h2, w0); FMA2(acc[2][1], h2, w1); FMA2(acc[2][2], h2, w2); FMA2(acc[2][3], h2, w3);
            FMA2(acc[3][0], h3, w0); FMA2(acc[3][1], h3, w1); FMA2(acc[3][2], h3, w2); FMA2(acc[3][3], h3, w3);
        }
        // ---- input part: k over I (x_t) ----
        #pragma unroll 4
        for (int k = 0; k < 28; ++k) {
            const float4 w4 = *reinterpret_cast<const float4*>(Ws + (64 + k) * 256 + j * 4);
            const ULL* xp = reinterpret_cast<const ULL*>(xb + k * LDH + rbase);
            const ULL h0 = xp[0], h1 = xp[1], h2 = xp[2], h3 = xp[3];
            const ULL w0 = pk2(w4.x, w4.x), w1 = pk2(w4.y, w4.y);
            const ULL w2 = pk2(w4.z, w4.z), w3 = pk2(w4.w, w4.w);
            FMA2(acc[0][0], h0, w0); FMA2(acc[0][1], h0, w1); FMA2(acc[0][2], h0, w2); FMA2(acc[0][3], h0, w3);
            FMA2(acc[1][0], h1, w0); FMA2(acc[1][1], h1, w1); FMA2(acc[1][2], h1, w2); FMA2(acc[1][3], h1, w3);
            FMA2(acc[2][0], h2, w0); FMA2(acc[2][1], h2, w1); FMA2(acc[2][2], h2, w2); FMA2(acc[2][3], h2, w3);
            FMA2(acc[3][0], h3, w0); FMA2(acc[3][1], h3, w1); FMA2(acc[3][2], h3, w2); FMA2(acc[3][3], h3, w3);
        }

        // ---- elementwise LSTM cell update (c stays in registers; HW tanh) ----
        float hnew[8];
        #pragma unroll
        for (int r2 = 0; r2 < 4; ++r2) {
            float gi0, gi1, gf0, gf1, gg0, gg1, go0, go1;
            upk2(acc[r2][0], gi0, gi1);
            upk2(acc[r2][1], gf0, gf1);
            upk2(acc[r2][2], gg0, gg1);
            upk2(acc[r2][3], go0, go1);
            {
                const int r = 2 * r2;
                float iv = sigf(gi0), fv = sigf(gf0), gv = tanhfast(gg0), ov = sigf(go0);
                creg[r] = fv * creg[r] + iv * gv;
                hnew[r] = ov * tanhfast(creg[r]);
            }
            {
                const int r = 2 * r2 + 1;
                float iv = sigf(gi1), fv = sigf(gf1), gv = tanhfast(gg1), ov = sigf(go1);
                creg[r] = fv * creg[r] + iv * gv;
                hnew[r] = ov * tanhfast(creg[r]);
            }
        }

        // write new h into the OTHER buffer; stage next x tile. No read-write hazard:
        // this step only read hT[t&1] / xT[t&1]; we write hT[(t+1)&1] / xT[(t+1)&1].
        {
            float* hd = hT + ((t + 1) & 1) * 64 * LDH + j * LDH + rbase;
            #pragma unroll
            for (int r = 0; r < 8; ++r) hd[r] = hnew[r];
        }
        if (pf) {
            float* xb2 = xT + ((t + 1) & 1) * 28 * LDH;
            #pragma unroll
            for (int u = 0; u < 4; ++u) {
                int e = u * NTHR + tid;
                if (e < RPB * I_) {
                    int r = e / 28, i2 = e - r * 28;
                    xb2[i2 * LDH + r] = xn[u];
                }
            }
        }
        __syncthreads();   // writes visible before next step reads them
    }

    // ---- final projection: out[b][o] = h_T[b] . Wout[o] + bout[o] ----
    const float* hf = hT + (T_ & 1) * 64 * LDH;
    for (int idx = tid; idx < RPB * O_; idx += NTHR) {
        int r = idx / O_, o = idx - r * O_;
        float s = bout[o];
        #pragma unroll
        for (int k = 0; k < 64; ++k)
            s += hf[k * LDH + r] * Wout[o * 64 + k];
        out[(row0 + r) * O_ + o] = s;
    }
}

extern "C" void kernel_launch(void* const* d_in, const int* in_sizes, int n_in,
                              void* d_out, int out_size)
{
    const float* x    = (const float*)d_in[0];
    const float* Wih  = (const float*)d_in[1];
    const float* Whh  = (const float*)d_in[2];
    const float* bih  = (const float*)d_in[3];
    const float* bhh  = (const float*)d_in[4];
    const float* Wout = (const float*)d_in[5];
    const float* bout = (const float*)d_in[6];
    float* out = (float*)d_out;

    const size_t smem = (size_t)SM_FLOATS * sizeof(float);  // ~107.5 KB per CTA
    cudaFuncSetAttribute(lstm_fused, cudaFuncAttributeMaxDynamicSharedMemorySize, (int)smem);
    lstm_fused<<<NBLK, NTHR, smem>>>(x, Wih, Whh, bih, bhh, Wout, bout, out);
}

// round 10
// speedup vs baseline: 1.3317x; 1.0425x over previous
#include <cuda_runtime.h>

typedef unsigned long long ULL;

// ---------------- f32x2 helpers (Blackwell packed fp32) ----------------
__device__ __forceinline__ ULL pk2(float a, float b) {
    ULL r; asm("mov.b64 %0, {%1, %2};" : "=l"(r) : "f"(a), "f"(b)); return r;
}
__device__ __forceinline__ void upk2(ULL v, float& a, float& b) {
    asm("mov.b64 {%0, %1}, %2;" : "=f"(a), "=f"(b) : "l"(v));
}
#define FMA2(acc, a, b) asm("fma.rn.f32x2 %0, %1, %2, %0;" : "+l"(acc) : "l"(a), "l"(b))

// ---------------- problem constants ----------------
constexpr int B_  = 4096;
constexpr int T_  = 128;
constexpr int I_  = 28;
constexpr int O_  = 10;
constexpr int RPB = 16;            // batch rows per block
constexpr int NBLK = B_ / RPB;     // 256 blocks (2 CTAs co-resident on most SMs)
constexpr int NTHR = 128;          // 64 units x 2 row-groups
constexpr int LDH  = 20;           // padded row stride (floats): 16B-aligned rows -> LDS.128 broadcasts

// shared memory layout (floats), per CTA
constexpr int WS_ELE  = 92 * 256;             // Ws[k][j*4+q], k: 0..63 = W_hh, 64..91 = W_ih
constexpr int HT_OFF  = WS_ELE;               // hT[2][64][LDH]  double buffer (unit-major)
constexpr int XT_OFF  = HT_OFF + 2 * 64 * LDH; // xT[2][28][LDH] double buffer
constexpr int SM_FLOATS = XT_OFF + 2 * 28 * LDH;   // 27232 floats = ~108.9 KB -> two CTAs/SM

// ---------------- activations: HW tanh (MUFU.TANH), sigmoid via tanh ----------------
__device__ __forceinline__ float tanhfast(float x) {
    float r; asm("tanh.approx.f32 %0, %1;" : "=f"(r) : "f"(x)); return r;
}
__device__ __forceinline__ float sigf(float x) {
    return fmaf(0.5f, tanhfast(0.5f * x), 0.5f);
}

__global__ void __launch_bounds__(NTHR, 2) lstm_fused(
    const float* __restrict__ x,     // [B, T, I]
    const float* __restrict__ Wih,   // [4H, I]
    const float* __restrict__ Whh,   // [4H, H]
    const float* __restrict__ bih,   // [4H]
    const float* __restrict__ bhh,   // [4H]
    const float* __restrict__ Wout,  // [O, H]
    const float* __restrict__ bout,  // [O]
    float* __restrict__ out)         // [B, O]
{
    extern __shared__ float sm[];
    float* Ws = sm;
    float* hT = sm + HT_OFF;   // two buffers of 64*LDH
    float* xT = sm + XT_OFF;

    const int tid   = threadIdx.x;
    const int j     = tid & 63;   // hidden unit owned by this thread
    const int ty    = tid >> 6;   // row group (0..1), 8 rows each
    const int rbase = ty * 8;
    const int row0  = blockIdx.x * RPB;

    // ---- stage weights into SMEM, gate-interleaved: Ws[k][j*4 + q], q in {i,f,g,o} ----
    for (int idx = tid; idx < 256 * 64; idx += NTHR) {        // W_hh[g][k]
        int g = idx >> 6, k = idx & 63;
        Ws[k * 256 + (g & 63) * 4 + (g >> 6)] = Whh[idx];
    }
    for (int idx = tid; idx < 256 * 28; idx += NTHR) {        // W_ih[g][k]
        int g = idx / 28, k = idx - g * 28;
        Ws[(64 + k) * 256 + (g & 63) * 4 + (g >> 6)] = Wih[idx];
    }
    for (int idx = tid; idx < 2 * 64 * LDH; idx += NTHR) hT[idx] = 0.0f;

    // biases (combined), replicated into f32x2
    const float b0 = bih[j]       + bhh[j];
    const float b1 = bih[64 + j]  + bhh[64 + j];
    const float b2 = bih[128 + j] + bhh[128 + j];
    const float b3 = bih[192 + j] + bhh[192 + j];
    const ULL bb[4] = { pk2(b0, b0), pk2(b1, b1), pk2(b2, b2), pk2(b3, b3) };

    // ---- preload x for t = 0 into buffer 0 ----  (RPB*I = 448 elements, 128 threads)
    #pragma unroll
    for (int u = 0; u < 4; ++u) {
        int e = u * NTHR + tid;
        if (e < RPB * I_) {
            int r = e / 28, i2 = e - r * 28;
            xT[i2 * LDH + r] = x[(row0 + r) * (T_ * I_) + 0 * I_ + i2];
        }
    }
    __syncthreads();

    float creg[8];
    #pragma unroll
    for (int r = 0; r < 8; ++r) creg[r] = 0.0f;

    // =================== time loop (ONE barrier per step) ===================
    for (int t = 0; t < T_; ++t) {
        // prefetch x for t+1 (LDG latency overlaps this step's compute)
        float xn[4];
        const bool pf = (t + 1 < T_);
        if (pf) {
            #pragma unroll
            for (int u = 0; u < 4; ++u) {
                int e = u * NTHR + tid;
                int e2 = (e < RPB * I_) ? e : 0;      // branch-free: clamp, lane 0 dup
                int r = e2 / 28, i2 = e2 - r * 28;
                xn[u] = x[(row0 + r) * (T_ * I_) + (t + 1) * I_ + i2];
            }
        }

        const float* xb = xT + (t & 1) * 28 * LDH;
        const float* hb = hT + (t & 1) * 64 * LDH;   // read buffer

        // accumulators: [row-pair r2][gate-type q], rows packed in f32x2 lanes
        ULL acc[4][4];
        #pragma unroll
        for (int r2 = 0; r2 < 4; ++r2)
            #pragma unroll
            for (int q = 0; q < 4; ++q)
                acc[r2][q] = bb[q];

        // ---- recurrent part: k over hidden units (h_{t-1}) ----
        #pragma unroll 8
        for (int k = 0; k < 64; ++k) {
            const float4 w4 = *reinterpret_cast<const float4*>(Ws + k * 256 + j * 4);
            const ulonglong2 hq0 = *reinterpret_cast<const ulonglong2*>(hb + k * LDH + rbase);     // rows 0-3 (bcast)
            const ulonglong2 hq1 = *reinterpret_cast<const ulonglong2*>(hb + k * LDH + rbase + 4); // rows 4-7 (bcast)
            const ULL h0 = hq0.x, h1 = hq0.y, h2 = hq1.x, h3 = hq1.y;
            const ULL w0 = pk2(w4.x, w4.x), w1 = pk2(w4.y, w4.y);
            const ULL w2 = pk2(w4.z, w4.z), w3 = pk2(w4.w, w4.w);
            FMA2(acc[0][0], h0, w0); FMA2(acc[0][1], h0, w1); FMA2(acc[0][2], h0, w2); FMA2(acc[0][3], h0, w3);
            FMA2(acc[1][0], h1, w0); FMA2(acc[1][1], h1, w1); FMA2(acc[1][2], h1, w2); FMA2(acc[1][3], h1, w3);
            FMA2(acc[2][0], h2, w0); FMA2(acc[2][1], h2, w1); FMA2(acc[2][2], h2, w2); FMA2(acc[2][3], h2, w3);
            FMA2(acc[3][0], h3, w0); FMA2(acc[3][1], h3, w1); FMA2(acc[3][2], h3, w2); FMA2(acc[3][3], h3, w3);
        }
        // ---- input part: k over I (x_t) ----
        #pragma unroll 4
        for (int k = 0; k < 28; ++k) {
            const float4 w4 = *reinterpret_cast<const float4*>(Ws + (64 + k) * 256 + j * 4);
            const ulonglong2 xq0 = *reinterpret_cast<const ulonglong2*>(xb + k * LDH + rbase);
            const ulonglong2 xq1 = *reinterpret_cast<const ulonglong2*>(xb + k * LDH + rbase + 4);
            const ULL h0 = xq0.x, h1 = xq0.y, h2 = xq1.x, h3 = xq1.y;
            const ULL w0 = pk2(w4.x, w4.x), w1 = pk2(w4.y, w4.y);
            const ULL w2 = pk2(w4.z, w4.z), w3 = pk2(w4.w, w4.w);
            FMA2(acc[0][0], h0, w0); FMA2(acc[0][1], h0, w1); FMA2(acc[0][2], h0, w2); FMA2(acc[0][3], h0, w3);
            FMA2(acc[1][0], h1, w0); FMA2(acc[1][1], h1, w1); FMA2(acc[1][2], h1, w2); FMA2(acc[1][3], h1, w3);
            FMA2(acc[2][0], h2, w0); FMA2(acc[2][1], h2, w1); FMA2(acc[2][2], h2, w2); FMA2(acc[2][3], h2, w3);
            FMA2(acc[3][0], h3, w0); FMA2(acc[3][1], h3, w1); FMA2(acc[3][2], h3, w2); FMA2(acc[3][3], h3, w3);
        }

        // ---- elementwise LSTM cell update (c stays in registers; HW tanh) ----
        float hnew[8];
        #pragma unroll
        for (int r2 = 0; r2 < 4; ++r2) {
            float gi0, gi1, gf0, gf1, gg0, gg1, go0, go1;
            upk2(acc[r2][0], gi0, gi1);
            upk2(acc[r2][1], gf0, gf1);
            upk2(acc[r2][2], gg0, gg1);
            upk2(acc[r2][3], go0, go1);
            {
                const int r = 2 * r2;
                float iv = sigf(gi0), fv = sigf(gf0), gv = tanhfast(gg0), ov = sigf(go0);
                creg[r] = fv * creg[r] + iv * gv;
                hnew[r] = ov * tanhfast(creg[r]);
            }
            {
                const int r = 2 * r2 + 1;
                float iv = sigf(gi1), fv = sigf(gf1), gv = tanhfast(gg1), ov = sigf(go1);
                creg[r] = fv * creg[r] + iv * gv;
                hnew[r] = ov * tanhfast(creg[r]);
            }
        }

        // write new h into the OTHER buffer; stage next x tile. No read-write hazard:
        // this step only read hT[t&1] / xT[t&1]; we write hT[(t+1)&1] / xT[(t+1)&1].
        {
            float* hd = hT + ((t + 1) & 1) * 64 * LDH + j * LDH + rbase;
            #pragma unroll
            for (int r = 0; r < 8; ++r) hd[r] = hnew[r];
        }
        if (pf) {
            float* xb2 = xT + ((t + 1) & 1) * 28 * LDH;
            #pragma unroll
            for (int u = 0; u < 4; ++u) {
                int e = u * NTHR + tid;
                if (e < RPB * I_) {
                    int r = e / 28, i2 = e - r * 28;
                    xb2[i2 * LDH + r] = xn[u];
                }
            }
        }
        __syncthreads();   // writes visible before next step reads them
    }

    // ---- final projection: out[b][o] = h_T[b] . Wout[o] + bout[o] ----
    const float* hf = hT + (T_ & 1) * 64 * LDH;
    for (int idx = tid; idx < RPB * O_; idx += NTHR) {
        int r = idx / O_, o = idx - r * O_;
        float s = bout[o];
        #pragma unroll
        for (int k = 0; k < 64; ++k)
            s += hf[k * LDH + r] * Wout[o * 64 + k];
        out[(row0 + r) * O_ + o] = s;
    }
}

extern "C" void kernel_launch(void* const* d_in, const int* in_sizes, int n_in,
                              void* d_out, int out_size)
{
    const float* x    = (const float*)d_in[0];
    const float* Wih  = (const float*)d_in[1];
    const float* Whh  = (const float*)d_in[2];
    const float* bih  = (const float*)d_in[3];
    const float* bhh  = (const float*)d_in[4];
    const float* Wout = (const float*)d_in[5];
    const float* bout = (const float*)d_in[6];
    float* out = (float*)d_out;

    const size_t smem = (size_t)SM_FLOATS * sizeof(float);  // ~108.9 KB per CTA
    cudaFuncSetAttribute(lstm_fused, cudaFuncAttributeMaxDynamicSharedMemorySize, (int)smem);
    lstm_fused<<<NBLK, NTHR, smem>>>(x, Wih, Whh, bih, bhh, Wout, bout, out);
}

// round 15
// speedup vs baseline: 1.8945x; 1.4226x over previous
#include <cuda_runtime.h>
#include <cstdint>

// ============================================================
// mma.sync tf32 LSTM (baseline PTX tensor path; tcgen05 is
// unavailable: harness PTX targets sm_103 without 'a').
// Per CTA: 32 batch rows. Per step:
//   gates[32x256] = A[32x96] * B[96x256]
// A = [h(64) | x(28) | pad4], col = gate*64 + unit.
// A and B stored in m16n8k8-fragment-native smem layouts.
// ============================================================

constexpr int T_   = 128;
constexpr int I_   = 28;
constexpr int O_   = 10;
constexpr int RPB  = 32;
constexpr int GRID = 4096 / RPB;   // 128
constexpr int NTHR = 256;          // 8 warps
constexpr int NKT  = 12;           // K = 96 = 12 * 8

// smem layout (floats)
constexpr int AF_BUF = 2 * NKT * 32 * 4;       // 3072 per buffer (2 m-tiles)
constexpr int BF_OFF = 2 * AF_BUF;             // 6144
constexpr int BF_SZ  = 8 * NKT * 32 * 8;       // 24576
constexpr int HO_OFF = BF_OFF + BF_SZ;         // 30720
constexpr int HOLD   = 66;
constexpr int WO_OFF = HO_OFF + 32 * HOLD;     // 32832
constexpr int SM_FLOATS = WO_OFF + 656;        // 33488 floats = ~131 KB

// ---------------- helpers ----------------
__device__ __forceinline__ uint32_t to_tf32(float f) {
    uint32_t r; asm("cvt.rna.tf32.f32 %0, %1;" : "=r"(r) : "f"(f)); return r;
}
__device__ __forceinline__ float tanhfast(float x) {
    float r; asm("tanh.approx.f32 %0, %1;" : "=f"(r) : "f"(x)); return r;
}
__device__ __forceinline__ float sigf(float x) { return fmaf(0.5f, tanhfast(0.5f * x), 0.5f); }

// m16n8k8 tf32 mma, accumulate in place
__device__ __forceinline__ void mma8(float* d, uint4 a, uint32_t b0, uint32_t b1) {
    asm volatile(
        "mma.sync.aligned.m16n8k8.row.col.f32.tf32.tf32.f32 "
        "{%0,%1,%2,%3},{%4,%5,%6,%7},{%8,%9},{%0,%1,%2,%3};"
        : "+f"(d[0]), "+f"(d[1]), "+f"(d[2]), "+f"(d[3])
        : "r"(a.x), "r"(a.y), "r"(a.z), "r"(a.w), "r"(b0), "r"(b1));
}

// A-fragment writer index (within one buffer, in uint32 units):
//   a0=A[r][c], a1=A[r+8][c], a2=A[r][c+4], a3=A[r+8][c+4]; r=lane>>2, c=lane&3
__device__ __forceinline__ int afW(int row, int k) {
    int mt = row >> 4, rr = row & 15;
    int ln = (rr & 7) * 4 + (k & 3);
    int e  = ((rr >> 3) & 1) | (((k >> 2) & 1) << 1);
    return (mt * NKT + (k >> 3)) * 128 + ln * 4 + e;
}

__global__ void __launch_bounds__(NTHR, 1) lstm_mma(
    const float* __restrict__ x,     // [B, T, I]
    const float* __restrict__ Wih,   // [4H, I]
    const float* __restrict__ Whh,   // [4H, H]
    const float* __restrict__ bih,   // [4H]
    const float* __restrict__ bhh,   // [4H]
    const float* __restrict__ Wout,  // [O, H]
    const float* __restrict__ bout,  // [O]
    float* __restrict__ out)         // [B, O]
{
    extern __shared__ float sm[];
    float* AF = sm;                 // A fragments, 2 buffers
    float* BF = sm + BF_OFF;        // B fragments
    float* HO = sm + HO_OFF;        // final h staging [32][HOLD]
    float* WO = sm + WO_OFF;        // Wout(640) + bout(10)
    uint32_t* AFu = reinterpret_cast<uint32_t*>(AF);
    const uint32_t* BFu = reinterpret_cast<const uint32_t*>(BF);

    const int tid  = threadIdx.x;
    const int wid  = tid >> 5;
    const int lane = tid & 31;
    const int row0 = blockIdx.x * RPB;
    const int u0   = wid * 8 + 2 * (lane & 3);   // first of this thread's 2 units

    // ---- build B fragments (one time): idx = ((w*12+kt)*32+ln)*8 + gate*2 + which ----
    for (int idx = tid; idx < BF_SZ; idx += NTHR) {
        int which = idx & 1, gate = (idx >> 1) & 3, ln = (idx >> 3) & 31;
        int wk = idx >> 8, kt = wk % NKT, w = wk / NKT;
        int k = kt * 8 + (ln & 3) + which * 4;
        int unit = w * 8 + (ln >> 2);
        int g4 = gate * 64 + unit;
        float v = 0.0f;
        if (k < 64)      v = Whh[g4 * 64 + k];
        else if (k < 92) v = Wih[g4 * 28 + (k - 64)];
        reinterpret_cast<uint32_t*>(BF)[idx] = to_tf32(v);
    }
    // ---- zero both A buffers (h0 = 0, pad cols = 0) ----
    for (int i = tid; i < 2 * AF_BUF; i += NTHR) AF[i] = 0.0f;
    // ---- stage Wout/bout ----
    for (int e = tid; e < 650; e += NTHR) WO[e] = (e < 640) ? Wout[e] : bout[e - 640];
    __syncthreads();

    // ---- stage x(t=0) into buffer 0 ----
    #pragma unroll
    for (int u = 0; u < 4; ++u) {
        int e = u * NTHR + tid;
        if (e < RPB * I_) {
            int r = e / 28, i2 = e - r * 28;
            AFu[afW(r, 64 + i2)] = to_tf32(x[(long)(row0 + r) * (T_ * I_) + i2]);
        }
    }

    // ---- per-thread bias (2 units x 4 gates) ----
    float bias[2][4];
    #pragma unroll
    for (int pi = 0; pi < 2; ++pi)
        #pragma unroll
        for (int g = 0; g < 4; ++g)
            bias[pi][g] = bih[g * 64 + u0 + pi] + bhh[g * 64 + u0 + pi];

    float creg[8];
    #pragma unroll
    for (int i = 0; i < 8; ++i) creg[i] = 0.0f;

    __syncthreads();

    // =================== time loop (one barrier per step) ===================
    for (int t = 0; t < T_; ++t) {
        // prefetch x_{t+1}
        float xn[4];
        const bool pf = (t + 1 < T_);
        if (pf) {
            #pragma unroll
            for (int u = 0; u < 4; ++u) {
                int e  = u * NTHR + tid;
                int e2 = (e < RPB * I_) ? e : 0;
                int r = e2 / 28, i2 = e2 - r * 28;
                xn[u] = x[(long)(row0 + r) * (T_ * I_) + (t + 1) * I_ + i2];
            }
        }

        const uint32_t* Ab = AFu + (t & 1) * AF_BUF;

        float d[2][4][4];
        #pragma unroll
        for (int m = 0; m < 2; ++m)
            #pragma unroll
            for (int g = 0; g < 4; ++g)
                #pragma unroll
                for (int e = 0; e < 4; ++e) d[m][g][e] = 0.0f;

        // ---- 96 mma: 12 k-tiles x (2 m-tiles x 4 gate-tiles) ----
        #pragma unroll
        for (int kt = 0; kt < NKT; ++kt) {
            uint4 a0 = *reinterpret_cast<const uint4*>(Ab + (0 * NKT + kt) * 128 + lane * 4);
            uint4 a1 = *reinterpret_cast<const uint4*>(Ab + (1 * NKT + kt) * 128 + lane * 4);
            const uint32_t* bp = BFu + ((wid * NKT + kt) * 32 + lane) * 8;
            uint4 bA = *reinterpret_cast<const uint4*>(bp);       // gates 0,1
            uint4 bB = *reinterpret_cast<const uint4*>(bp + 4);   // gates 2,3
            mma8(d[0][0], a0, bA.x, bA.y); mma8(d[0][1], a0, bA.z, bA.w);
            mma8(d[0][2], a0, bB.x, bB.y); mma8(d[0][3], a0, bB.z, bB.w);
            mma8(d[1][0], a1, bA.x, bA.y); mma8(d[1][1], a1, bA.z, bA.w);
            mma8(d[1][2], a1, bB.x, bB.y); mma8(d[1][3], a1, bB.z, bB.w);
        }

        // ---- epilogue: 8 cells/thread (4 rows x 2 units), fully local ----
        uint32_t* An = AFu + ((t + 1) & 1) * AF_BUF;
        #pragma unroll
        for (int ri = 0; ri < 4; ++ri) {
            const int mt = ri >> 1, ro = ri & 1;
            const int row = (lane >> 2) + ro * 8 + mt * 16;
            #pragma unroll
            for (int pi = 0; pi < 2; ++pi) {
                float gi = d[mt][0][ro * 2 + pi] + bias[pi][0];
                float gf = d[mt][1][ro * 2 + pi] + bias[pi][1];
                float gg = d[mt][2][ro * 2 + pi] + bias[pi][2];
                float go = d[mt][3][ro * 2 + pi] + bias[pi][3];
                const int ci = ri * 2 + pi;
                creg[ci] = sigf(gf) * creg[ci] + sigf(gi) * tanhfast(gg);
                float h = sigf(go) * tanhfast(creg[ci]);
                if (t < T_ - 1) An[afW(row, u0 + pi)] = to_tf32(h);
                else            HO[row * HOLD + (u0 + pi)] = h;
            }
        }

        // ---- stage x_{t+1} into next buffer ----
        if (pf) {
            #pragma unroll
            for (int u = 0; u < 4; ++u) {
                int e = u * NTHR + tid;
                if (e < RPB * I_) {
                    int r = e / 28, i2 = e - r * 28;
                    An[afW(r, 64 + i2)] = to_tf32(xn[u]);
                }
            }
        }
        __syncthreads();
    }

    // ---- final projection: out[b][o] = h_T . Wout[o] + bout[o] ----
    for (int e = tid; e < RPB * O_; e += NTHR) {
        int r = e / O_, o = e - r * O_;
        float s = WO[640 + o];
        #pragma unroll
        for (int k = 0; k < 64; ++k)
            s += HO[r * HOLD + k] * WO[o * 64 + k];
        out[(long)(row0 + r) * O_ + o] = s;
    }
}

extern "C" void kernel_launch(void* const* d_in, const int* in_sizes, int n_in,
                              void* d_out, int out_size)
{
    const float* x    = (const float*)d_in[0];
    const float* Wih  = (const float*)d_in[1];
    const float* Whh  = (const float*)d_in[2];
    const float* bih  = (const float*)d_in[3];
    const float* bhh  = (const float*)d_in[4];
    const float* Wout = (const float*)d_in[5];
    const float* bout = (const float*)d_in[6];
    float* out = (float*)d_out;

    const size_t smem = (size_t)SM_FLOATS * sizeof(float);  // ~131 KB
    cudaFuncSetAttribute(lstm_mma, cudaFuncAttributeMaxDynamicSharedMemorySize, (int)smem);
    lstm_mma<<<GRID, NTHR, smem>>>(x, Wih, Whh, bih, bhh, Wout, bout, out);
}